// round 15
// baseline (speedup 1.0000x reference)
#include <cuda_runtime.h>
#include <math.h>

#define C 100            // number of classes
#define D 256            // feature dim
#define PCAP (1 << 20)   // capacity of the sorted-index scratch (N = 500000)
#define SUM_BLOCKS 296   // 2 blocks/SM -> exactly one wave for pass B
#define DIST_ROWS 6      // rows per warp in the distance pass
#define PA_BLOCKS 1184   // 8 blocks/SM for the latency-bound pass-A kernels

__device__ float g_sums[C * D];
__device__ int   g_counti[C];      // int histogram
__device__ int   g_cursor[C];      // scatter cursors (start at 0)
__device__ int   g_packed[PCAP];   // (label << 24) | row, sorted by label

// ---------------------------------------------------------------------------
// Pure zeroing kernel (no label reads -> shortest possible serial prefix).
// ---------------------------------------------------------------------------
__global__ void k_zero() {
    int i = blockIdx.x * blockDim.x + threadIdx.x;
    if (i < C * D) g_sums[i] = 0.0f;
    if (i < C)   { g_counti[i] = 0; g_cursor[i] = 0; }
}

// ---------------------------------------------------------------------------
// Per-block label-dtype detection from a fixed in-bounds window.
// Words 1,3,...,511 exist for BOTH dtypes. int64 LE labels < 2^31 => every
// odd word is 0; int32 labels uniform 0..99 => some odd word among 256
// samples is nonzero (prob 1 - 0.01^256).
// ---------------------------------------------------------------------------
__device__ __forceinline__ int block_is64(const unsigned int* __restrict__ lw,
                                          int N, int tid) {
    __shared__ int s;
    if (tid == 0) s = 1;
    __syncthreads();
    const int pairs = min(N / 2, 256);
    if (tid < pairs && lw[2 * tid + 1] != 0u) s = 0;
    __syncthreads();
    return s;
}

__device__ __forceinline__ int load_label(const int* __restrict__ l32, int i, int is64) {
    return __ldg(&l32[is64 ? (i << 1) : i]);
}

// ---------------------------------------------------------------------------
// Pass A1: label histogram (block-local smem, one flush per block).
// ---------------------------------------------------------------------------
__global__ void k_hist(const int* __restrict__ l32, int N, int rows_per_block) {
    __shared__ int h[C];
    const int tid = threadIdx.x;
    const int is64 = block_is64((const unsigned int*)l32, N, tid);
    for (int i = tid; i < C; i += blockDim.x) h[i] = 0;
    __syncthreads();
    const int r0 = blockIdx.x * rows_per_block;
    const int r1 = min(r0 + rows_per_block, N);
    for (int i = r0 + tid; i < r1; i += blockDim.x)
        atomicAdd(&h[load_label(l32, i, is64)], 1);
    __syncthreads();
    for (int i = tid; i < C; i += blockDim.x)
        if (h[i]) atomicAdd(&g_counti[i], h[i]);
}

// ---------------------------------------------------------------------------
// Pass A2: scatter (label<<24 | row) into class-sorted order. Each block
// recomputes the 100-wide exclusive scan from g_counti locally (L2 hits).
// Block-local histogram reserves a per-class range with ONE global atomic
// per class (cursors start at 0).
// ---------------------------------------------------------------------------
__global__ void k_scatter(const int* __restrict__ l32, int N, int rows_per_block) {
    __shared__ int h[C];
    __shared__ int base[C];
    __shared__ int sc[128];

    const int tid = threadIdx.x;
    const int is64 = block_is64((const unsigned int*)l32, N, tid);
    for (int i = tid; i < C; i += blockDim.x) h[i] = 0;
    if (tid < 128) sc[tid] = (tid < C) ? __ldg(&g_counti[tid]) : 0;
    __syncthreads();

    #pragma unroll
    for (int off = 1; off < 128; off <<= 1) {
        int t = (tid >= off && tid < 128) ? sc[tid - off] : 0;
        __syncthreads();
        if (tid < 128) sc[tid] += t;
        __syncthreads();
    }

    const int r0 = blockIdx.x * rows_per_block;
    const int r1 = min(r0 + rows_per_block, N);
    for (int i = r0 + tid; i < r1; i += blockDim.x)
        atomicAdd(&h[load_label(l32, i, is64)], 1);
    __syncthreads();

    for (int i = tid; i < C; i += blockDim.x) {
        const int start = sc[i] - __ldg(&g_counti[i]);   // exclusive scan
        base[i] = start + atomicAdd(&g_cursor[i], h[i]);
        h[i] = 0;
    }
    __syncthreads();
    for (int i = r0 + tid; i < r1; i += blockDim.x) {
        const int lab = load_label(l32, i, is64);
        const int loc = atomicAdd(&h[lab], 1);
        g_packed[base[lab] + loc] = (lab << 24) | i;
    }
}

// ---------------------------------------------------------------------------
// Pass B: segment-sum over class-sorted rows. EXACTLY ONE WAVE (296 blocks =
// 2/SM); each warp owns a contiguous chunk of sorted positions. Lane
// accumulates 8 dims (2x float4) in registers, flush to g_sums only on class
// change (~1/warp). Depth-2 pipeline of 4-row batches. [R13: 82.3us, 79% DRAM]
// ---------------------------------------------------------------------------
__global__ void __launch_bounds__(256, 2)
k_sum_sorted(const float* __restrict__ feat, int total, int chunk) {
    const int gw   = (int)((blockIdx.x * blockDim.x + threadIdx.x) >> 5);
    const int lane = threadIdx.x & 31;
    const int p0 = gw * chunk;
    const int p1 = min(p0 + chunk, total);
    if (p0 >= p1) return;

    float4 a0 = make_float4(0, 0, 0, 0);
    float4 a1 = make_float4(0, 0, 0, 0);
    int cur = __ldg(&g_packed[p0]) >> 24;

#define FLUSH()                                                               \
    do {                                                                      \
        float* dp = &g_sums[cur * D + (lane << 2)];                           \
        atomicAdd(dp + 0, a0.x); atomicAdd(dp + 1, a0.y);                     \
        atomicAdd(dp + 2, a0.z); atomicAdd(dp + 3, a0.w);                     \
        atomicAdd(dp + 128, a1.x); atomicAdd(dp + 129, a1.y);                 \
        atomicAdd(dp + 130, a1.z); atomicAdd(dp + 131, a1.w);                 \
        a0.x = a0.y = a0.z = a0.w = 0.0f;                                     \
        a1.x = a1.y = a1.z = a1.w = 0.0f;                                     \
    } while (0)

    int pkA[4], pkB[4];
    float4 vaA[4], vbA[4], vaB[4], vbB[4];

#define PLOAD(PK, VA, VB, P, M)                                               \
    do {                                                                      \
        _Pragma("unroll")                                                     \
        for (int j = 0; j < 4; j++) if (j < (M)) {                            \
            (PK)[j] = __ldg(&g_packed[(P) + j]);                              \
            const float4* f4 =                                                \
                (const float4*)(feat + (size_t)((PK)[j] & 0xFFFFFF) * D);     \
            (VA)[j] = __ldcs(&f4[lane]);                                      \
            (VB)[j] = __ldcs(&f4[lane + 32]);                                 \
        }                                                                     \
    } while (0)

#define PPROC(PK, VA, VB, M)                                                  \
    do {                                                                      \
        _Pragma("unroll")                                                     \
        for (int j = 0; j < 4; j++) if (j < (M)) {                            \
            const int lab = (PK)[j] >> 24;                                    \
            if (lab != cur) { FLUSH(); cur = lab; }                           \
            a0.x += (VA)[j].x; a0.y += (VA)[j].y;                             \
            a0.z += (VA)[j].z; a0.w += (VA)[j].w;                             \
            a1.x += (VB)[j].x; a1.y += (VB)[j].y;                             \
            a1.z += (VB)[j].z; a1.w += (VB)[j].w;                             \
        }                                                                     \
    } while (0)

    int p = p0;
    int m = min(4, p1 - p);
    PLOAD(pkA, vaA, vbA, p, m);
    int pn = p + m;
    int useA = 1;
    while (pn < p1) {
        const int mn = min(4, p1 - pn);
        if (useA) {
            PLOAD(pkB, vaB, vbB, pn, mn);
            PPROC(pkA, vaA, vbA, m);
        } else {
            PLOAD(pkA, vaA, vbA, pn, mn);
            PPROC(pkB, vaB, vbB, m);
        }
        useA ^= 1;
        pn += mn;
        m = mn;
    }
    if (useA) {
        PPROC(pkA, vaA, vbA, m);
    } else {
        PPROC(pkB, vaB, vbB, m);
    }
    FLUSH();

#undef PLOAD
#undef PPROC
#undef FLUSH
}

// ---------------------------------------------------------------------------
// k_dist: distance to own-class center, class-sorted order, oversubscribed
// grid (measured-best regime). SIX rows per warp to amortize the pk load and
// shfl/sqrt epilogue. Center row L1-resident within a class run; computed on
// the fly as sums*inv_cnt.
// ---------------------------------------------------------------------------
__global__ void __launch_bounds__(256)
k_dist(const float* __restrict__ feat, float* __restrict__ out, int N) {
    const int gw   = (int)((blockIdx.x * blockDim.x + threadIdx.x) >> 5);
    const int lane = threadIdx.x & 31;
    const int p0 = DIST_ROWS * gw;
    if (p0 >= N) return;
    const int nr = min(DIST_ROWS, N - p0);

    int pk[DIST_ROWS];
    #pragma unroll
    for (int j = 0; j < DIST_ROWS; j++)
        pk[j] = (j < nr) ? __ldg(&g_packed[p0 + j]) : __ldg(&g_packed[p0]);

    float4 fa[DIST_ROWS], fb[DIST_ROWS], sa[DIST_ROWS], sb[DIST_ROWS];
    #pragma unroll
    for (int j = 0; j < DIST_ROWS; j++) {
        const float4* f4 =
            (const float4*)(feat + (size_t)(pk[j] & 0xFFFFFF) * D);
        fa[j] = __ldcs(&f4[lane]);
        fb[j] = __ldcs(&f4[lane + 32]);
    }
    #pragma unroll
    for (int j = 0; j < DIST_ROWS; j++) {
        const float4* s4 = (const float4*)(g_sums + (size_t)(pk[j] >> 24) * D);
        sa[j] = __ldg(&s4[lane]);
        sb[j] = __ldg(&s4[lane + 32]);
    }

    float dsq[DIST_ROWS];
    #pragma unroll
    for (int j = 0; j < DIST_ROWS; j++) {
        const int cnt = __ldg(&g_counti[pk[j] >> 24]);
        const float inv = (cnt > 0) ? (1.0f / (float)cnt) : 0.0f;
        float s = 0.0f, dx;
        dx = fa[j].x - sa[j].x * inv; s = fmaf(dx, dx, s);
        dx = fa[j].y - sa[j].y * inv; s = fmaf(dx, dx, s);
        dx = fa[j].z - sa[j].z * inv; s = fmaf(dx, dx, s);
        dx = fa[j].w - sa[j].w * inv; s = fmaf(dx, dx, s);
        dx = fb[j].x - sb[j].x * inv; s = fmaf(dx, dx, s);
        dx = fb[j].y - sb[j].y * inv; s = fmaf(dx, dx, s);
        dx = fb[j].z - sb[j].z * inv; s = fmaf(dx, dx, s);
        dx = fb[j].w - sb[j].w * inv; s = fmaf(dx, dx, s);
        dsq[j] = s;
    }

    #pragma unroll
    for (int o = 16; o; o >>= 1) {
        #pragma unroll
        for (int j = 0; j < DIST_ROWS; j++)
            dsq[j] += __shfl_xor_sync(0xffffffffu, dsq[j], o);
    }
    if (lane == 0) {
        #pragma unroll
        for (int j = 0; j < DIST_ROWS; j++)
            if (j < nr) out[pk[j] & 0xFFFFFF] = sqrtf(dsq[j]);
    }
}

// ---------------------------------------------------------------------------
extern "C" void kernel_launch(void* const* d_in, const int* in_sizes, int n_in,
                              void* d_out, int out_size) {
    const float* feat = (const float*)d_in[0];
    const int*   l32  = (const int*)d_in[1];
    float* out = (float*)d_out;

    const int N = in_sizes[0] / D;             // 500000

    k_zero<<<(C * D + 255) / 256, 256>>>();
    {
        int rpb = (N + PA_BLOCKS - 1) / PA_BLOCKS;   // 423
        k_hist<<<PA_BLOCKS, 256>>>(l32, N, rpb);
    }
    {
        int rpb = (N + PA_BLOCKS - 1) / PA_BLOCKS;
        k_scatter<<<PA_BLOCKS, 256>>>(l32, N, rpb);
    }
    {
        const int warps = SUM_BLOCKS * 8;
        const int chunk = (N + warps - 1) / warps;    // 212 for N=500000
        k_sum_sorted<<<SUM_BLOCKS, 256>>>(feat, N, chunk);
    }
    {
        int rows_per_block = 8 * DIST_ROWS;     // 8 warps x 6 sorted rows
        int blocks = (N + rows_per_block - 1) / rows_per_block;
        k_dist<<<blocks, 256>>>(feat, out, N);
    }
}

// round 16
// speedup vs baseline: 1.0899x; 1.0899x over previous
#include <cuda_runtime.h>
#include <math.h>

#define C 100            // number of classes
#define D 256            // feature dim
#define PCAP (1 << 20)   // capacity of the sorted-index scratch (N = 500000)
#define SUM_BLOCKS 296   // 2 blocks/SM -> exactly one wave for pass B
#define DIST_ROWS 4      // rows per warp in the distance pass (48 regs, best)
#define PA_BLOCKS 592    // 4 blocks/SM for the pass-A kernels

__device__ float g_sums[C * D];
__device__ int   g_counti[C];      // int histogram
__device__ int   g_cursor[C];      // scatter cursors (start at 0)
__device__ int   g_packed[PCAP];   // (label << 24) | row, sorted by label

// ---------------------------------------------------------------------------
// Minimal zeroing: only the 200 ints the pass-A kernels depend on.
// (g_sums zeroing is folded into k_scatter, hidden under its label pass.)
// ---------------------------------------------------------------------------
__global__ void k_zero() {
    int i = threadIdx.x;
    if (i < C) { g_counti[i] = 0; g_cursor[i] = 0; }
}

// ---------------------------------------------------------------------------
// Per-block label-dtype detection from a fixed in-bounds window.
// Words 1,3,...,511 exist for BOTH dtypes. int64 LE labels < 2^31 => every
// odd word is 0; int32 labels uniform 0..99 => some odd word among 256
// samples is nonzero (prob 1 - 0.01^256).
// ---------------------------------------------------------------------------
__device__ __forceinline__ int block_is64(const unsigned int* __restrict__ lw,
                                          int N, int tid) {
    __shared__ int s;
    if (tid == 0) s = 1;
    __syncthreads();
    const int pairs = min(N / 2, 256);
    if (tid < pairs && lw[2 * tid + 1] != 0u) s = 0;
    __syncthreads();
    return s;
}

__device__ __forceinline__ int load_label(const int* __restrict__ l32, int i, int is64) {
    return __ldg(&l32[is64 ? (i << 1) : i]);
}

// ---------------------------------------------------------------------------
// Pass A1: label histogram (block-local smem, one flush per block).
// ---------------------------------------------------------------------------
__global__ void k_hist(const int* __restrict__ l32, int N, int rows_per_block) {
    __shared__ int h[C];
    const int tid = threadIdx.x;
    const int is64 = block_is64((const unsigned int*)l32, N, tid);
    for (int i = tid; i < C; i += blockDim.x) h[i] = 0;
    __syncthreads();
    const int r0 = blockIdx.x * rows_per_block;
    const int r1 = min(r0 + rows_per_block, N);
    for (int i = r0 + tid; i < r1; i += blockDim.x)
        atomicAdd(&h[load_label(l32, i, is64)], 1);
    __syncthreads();
    for (int i = tid; i < C; i += blockDim.x)
        if (h[i]) atomicAdd(&g_counti[i], h[i]);
}

// ---------------------------------------------------------------------------
// Pass A2: scatter (label<<24 | row) into class-sorted order + zero g_sums
// (each block zeroes its 1/PA_BLOCKS slice — hidden under the label pass;
// the kernel boundary orders it before pass B). Each block recomputes the
// 100-wide exclusive scan from g_counti locally (L2 hits); block-local
// histogram reserves a per-class range with ONE global atomic per class.
// ---------------------------------------------------------------------------
__global__ void k_scatter(const int* __restrict__ l32, int N, int rows_per_block) {
    __shared__ int h[C];
    __shared__ int base[C];
    __shared__ int sc[128];

    const int tid = threadIdx.x;

    // zero this block's slice of g_sums (25600 / 592 ~= 44 floats)
    {
        const int per = (C * D + PA_BLOCKS - 1) / PA_BLOCKS;
        const int z0 = blockIdx.x * per;
        const int z1 = min(z0 + per, C * D);
        for (int i = z0 + tid; i < z1; i += blockDim.x) g_sums[i] = 0.0f;
    }

    const int is64 = block_is64((const unsigned int*)l32, N, tid);
    for (int i = tid; i < C; i += blockDim.x) h[i] = 0;
    if (tid < 128) sc[tid] = (tid < C) ? __ldg(&g_counti[tid]) : 0;
    __syncthreads();

    #pragma unroll
    for (int off = 1; off < 128; off <<= 1) {
        int t = (tid >= off && tid < 128) ? sc[tid - off] : 0;
        __syncthreads();
        if (tid < 128) sc[tid] += t;
        __syncthreads();
    }

    const int r0 = blockIdx.x * rows_per_block;
    const int r1 = min(r0 + rows_per_block, N);
    for (int i = r0 + tid; i < r1; i += blockDim.x)
        atomicAdd(&h[load_label(l32, i, is64)], 1);
    __syncthreads();

    for (int i = tid; i < C; i += blockDim.x) {
        const int start = sc[i] - __ldg(&g_counti[i]);   // exclusive scan
        base[i] = start + atomicAdd(&g_cursor[i], h[i]);
        h[i] = 0;
    }
    __syncthreads();
    for (int i = r0 + tid; i < r1; i += blockDim.x) {
        const int lab = load_label(l32, i, is64);
        const int loc = atomicAdd(&h[lab], 1);
        g_packed[base[lab] + loc] = (lab << 24) | i;
    }
}

// ---------------------------------------------------------------------------
// Pass B: segment-sum over class-sorted rows. EXACTLY ONE WAVE (296 blocks =
// 2/SM); each warp owns a contiguous chunk of sorted positions. Lane
// accumulates 8 dims (2x float4) in registers, flush to g_sums only on class
// change (~1/warp). Depth-2 pipeline of 4-row batches. [R13: 82.3us, 79% DRAM]
// ---------------------------------------------------------------------------
__global__ void __launch_bounds__(256, 2)
k_sum_sorted(const float* __restrict__ feat, int total, int chunk) {
    const int gw   = (int)((blockIdx.x * blockDim.x + threadIdx.x) >> 5);
    const int lane = threadIdx.x & 31;
    const int p0 = gw * chunk;
    const int p1 = min(p0 + chunk, total);
    if (p0 >= p1) return;

    float4 a0 = make_float4(0, 0, 0, 0);
    float4 a1 = make_float4(0, 0, 0, 0);
    int cur = __ldg(&g_packed[p0]) >> 24;

#define FLUSH()                                                               \
    do {                                                                      \
        float* dp = &g_sums[cur * D + (lane << 2)];                           \
        atomicAdd(dp + 0, a0.x); atomicAdd(dp + 1, a0.y);                     \
        atomicAdd(dp + 2, a0.z); atomicAdd(dp + 3, a0.w);                     \
        atomicAdd(dp + 128, a1.x); atomicAdd(dp + 129, a1.y);                 \
        atomicAdd(dp + 130, a1.z); atomicAdd(dp + 131, a1.w);                 \
        a0.x = a0.y = a0.z = a0.w = 0.0f;                                     \
        a1.x = a1.y = a1.z = a1.w = 0.0f;                                     \
    } while (0)

    int pkA[4], pkB[4];
    float4 vaA[4], vbA[4], vaB[4], vbB[4];

#define PLOAD(PK, VA, VB, P, M)                                               \
    do {                                                                      \
        _Pragma("unroll")                                                     \
        for (int j = 0; j < 4; j++) if (j < (M)) {                            \
            (PK)[j] = __ldg(&g_packed[(P) + j]);                              \
            const float4* f4 =                                                \
                (const float4*)(feat + (size_t)((PK)[j] & 0xFFFFFF) * D);     \
            (VA)[j] = __ldcs(&f4[lane]);                                      \
            (VB)[j] = __ldcs(&f4[lane + 32]);                                 \
        }                                                                     \
    } while (0)

#define PPROC(PK, VA, VB, M)                                                  \
    do {                                                                      \
        _Pragma("unroll")                                                     \
        for (int j = 0; j < 4; j++) if (j < (M)) {                            \
            const int lab = (PK)[j] >> 24;                                    \
            if (lab != cur) { FLUSH(); cur = lab; }                           \
            a0.x += (VA)[j].x; a0.y += (VA)[j].y;                             \
            a0.z += (VA)[j].z; a0.w += (VA)[j].w;                             \
            a1.x += (VB)[j].x; a1.y += (VB)[j].y;                             \
            a1.z += (VB)[j].z; a1.w += (VB)[j].w;                             \
        }                                                                     \
    } while (0)

    int p = p0;
    int m = min(4, p1 - p);
    PLOAD(pkA, vaA, vbA, p, m);
    int pn = p + m;
    int useA = 1;
    while (pn < p1) {
        const int mn = min(4, p1 - pn);
        if (useA) {
            PLOAD(pkB, vaB, vbB, pn, mn);
            PPROC(pkA, vaA, vbA, m);
        } else {
            PLOAD(pkA, vaA, vbA, pn, mn);
            PPROC(pkB, vaB, vbB, m);
        }
        useA ^= 1;
        pn += mn;
        m = mn;
    }
    if (useA) {
        PPROC(pkA, vaA, vbA, m);
    } else {
        PPROC(pkB, vaB, vbB, m);
    }
    FLUSH();

#undef PLOAD
#undef PPROC
#undef FLUSH
}

// ---------------------------------------------------------------------------
// k_dist: distance to own-class center, class-sorted order (measured-best
// config: 4 rows/warp, oversubscribed grid). Center row L1-resident within a
// class run; computed on the fly as sums*inv_cnt.
// ---------------------------------------------------------------------------
__global__ void __launch_bounds__(256)
k_dist(const float* __restrict__ feat, float* __restrict__ out, int N) {
    const int gw   = (int)((blockIdx.x * blockDim.x + threadIdx.x) >> 5);
    const int lane = threadIdx.x & 31;
    const int p0 = DIST_ROWS * gw;
    if (p0 >= N) return;
    const int nr = min(DIST_ROWS, N - p0);

    int pk[DIST_ROWS];
    #pragma unroll
    for (int j = 0; j < DIST_ROWS; j++)
        pk[j] = (j < nr) ? __ldg(&g_packed[p0 + j]) : __ldg(&g_packed[p0]);

    float4 fa[DIST_ROWS], fb[DIST_ROWS], sa[DIST_ROWS], sb[DIST_ROWS];
    #pragma unroll
    for (int j = 0; j < DIST_ROWS; j++) {
        const float4* f4 =
            (const float4*)(feat + (size_t)(pk[j] & 0xFFFFFF) * D);
        fa[j] = __ldcs(&f4[lane]);
        fb[j] = __ldcs(&f4[lane + 32]);
    }
    #pragma unroll
    for (int j = 0; j < DIST_ROWS; j++) {
        const float4* s4 = (const float4*)(g_sums + (size_t)(pk[j] >> 24) * D);
        sa[j] = __ldg(&s4[lane]);
        sb[j] = __ldg(&s4[lane + 32]);
    }

    float dsq[DIST_ROWS];
    #pragma unroll
    for (int j = 0; j < DIST_ROWS; j++) {
        const int cnt = __ldg(&g_counti[pk[j] >> 24]);
        const float inv = (cnt > 0) ? (1.0f / (float)cnt) : 0.0f;
        float s = 0.0f, dx;
        dx = fa[j].x - sa[j].x * inv; s = fmaf(dx, dx, s);
        dx = fa[j].y - sa[j].y * inv; s = fmaf(dx, dx, s);
        dx = fa[j].z - sa[j].z * inv; s = fmaf(dx, dx, s);
        dx = fa[j].w - sa[j].w * inv; s = fmaf(dx, dx, s);
        dx = fb[j].x - sb[j].x * inv; s = fmaf(dx, dx, s);
        dx = fb[j].y - sb[j].y * inv; s = fmaf(dx, dx, s);
        dx = fb[j].z - sb[j].z * inv; s = fmaf(dx, dx, s);
        dx = fb[j].w - sb[j].w * inv; s = fmaf(dx, dx, s);
        dsq[j] = s;
    }

    #pragma unroll
    for (int o = 16; o; o >>= 1) {
        #pragma unroll
        for (int j = 0; j < DIST_ROWS; j++)
            dsq[j] += __shfl_xor_sync(0xffffffffu, dsq[j], o);
    }
    if (lane == 0) {
        #pragma unroll
        for (int j = 0; j < DIST_ROWS; j++)
            if (j < nr) out[pk[j] & 0xFFFFFF] = sqrtf(dsq[j]);
    }
}

// ---------------------------------------------------------------------------
extern "C" void kernel_launch(void* const* d_in, const int* in_sizes, int n_in,
                              void* d_out, int out_size) {
    const float* feat = (const float*)d_in[0];
    const int*   l32  = (const int*)d_in[1];
    float* out = (float*)d_out;

    const int N = in_sizes[0] / D;             // 500000

    k_zero<<<1, 128>>>();
    {
        int rpb = (N + PA_BLOCKS - 1) / PA_BLOCKS;
        k_hist<<<PA_BLOCKS, 256>>>(l32, N, rpb);
    }
    {
        int rpb = (N + PA_BLOCKS - 1) / PA_BLOCKS;
        k_scatter<<<PA_BLOCKS, 256>>>(l32, N, rpb);
    }
    {
        const int warps = SUM_BLOCKS * 8;
        const int chunk = (N + warps - 1) / warps;    // 212 for N=500000
        k_sum_sorted<<<SUM_BLOCKS, 256>>>(feat, N, chunk);
    }
    {
        int rows_per_block = 8 * DIST_ROWS;     // 8 warps x 4 sorted rows
        int blocks = (N + rows_per_block - 1) / rows_per_block;
        k_dist<<<blocks, 256>>>(feat, out, N);
    }
}

// round 17
// speedup vs baseline: 1.1121x; 1.0204x over previous
#include <cuda_runtime.h>
#include <math.h>

#define C 100            // number of classes
#define D 256            // feature dim
#define PCAP (1 << 20)   // capacity of the sorted-index scratch (N = 500000)
#define SUM_BLOCKS 444   // 3 blocks/SM -> exactly one wave for pass B
#define PB_B 3           // rows per pipelined batch (keeps regs <= 85)
#define DIST_ROWS 4      // rows per warp in the distance pass (48 regs, best)
#define PA_BLOCKS 592    // 4 blocks/SM for the pass-A kernels

__device__ float g_sums[C * D];
__device__ int   g_counti[C];      // int histogram
__device__ int   g_cursor[C];      // scatter cursors (start at 0)
__device__ int   g_packed[PCAP];   // (label << 24) | row, sorted by label

// ---------------------------------------------------------------------------
// Minimal zeroing: only the 200 ints the pass-A kernels depend on.
// (g_sums zeroing is folded into k_scatter, hidden under its label pass.)
// ---------------------------------------------------------------------------
__global__ void k_zero() {
    int i = threadIdx.x;
    if (i < C) { g_counti[i] = 0; g_cursor[i] = 0; }
}

// ---------------------------------------------------------------------------
// Per-block label-dtype detection from a fixed in-bounds window.
// Words 1,3,...,511 exist for BOTH dtypes. int64 LE labels < 2^31 => every
// odd word is 0; int32 labels uniform 0..99 => some odd word among 256
// samples is nonzero (prob 1 - 0.01^256).
// ---------------------------------------------------------------------------
__device__ __forceinline__ int block_is64(const unsigned int* __restrict__ lw,
                                          int N, int tid) {
    __shared__ int s;
    if (tid == 0) s = 1;
    __syncthreads();
    const int pairs = min(N / 2, 256);
    if (tid < pairs && lw[2 * tid + 1] != 0u) s = 0;
    __syncthreads();
    return s;
}

__device__ __forceinline__ int load_label(const int* __restrict__ l32, int i, int is64) {
    return __ldg(&l32[is64 ? (i << 1) : i]);
}

// ---------------------------------------------------------------------------
// Pass A1: label histogram (block-local smem, one flush per block).
// ---------------------------------------------------------------------------
__global__ void k_hist(const int* __restrict__ l32, int N, int rows_per_block) {
    __shared__ int h[C];
    const int tid = threadIdx.x;
    const int is64 = block_is64((const unsigned int*)l32, N, tid);
    for (int i = tid; i < C; i += blockDim.x) h[i] = 0;
    __syncthreads();
    const int r0 = blockIdx.x * rows_per_block;
    const int r1 = min(r0 + rows_per_block, N);
    for (int i = r0 + tid; i < r1; i += blockDim.x)
        atomicAdd(&h[load_label(l32, i, is64)], 1);
    __syncthreads();
    for (int i = tid; i < C; i += blockDim.x)
        if (h[i]) atomicAdd(&g_counti[i], h[i]);
}

// ---------------------------------------------------------------------------
// Pass A2: scatter (label<<24 | row) into class-sorted order + zero g_sums
// (each block zeroes its slice — hidden under the label pass; the kernel
// boundary orders it before pass B). Each block recomputes the 100-wide
// exclusive scan from g_counti locally (L2 hits); block-local histogram
// reserves a per-class range with ONE global atomic per class.
// ---------------------------------------------------------------------------
__global__ void k_scatter(const int* __restrict__ l32, int N, int rows_per_block) {
    __shared__ int h[C];
    __shared__ int base[C];
    __shared__ int sc[128];

    const int tid = threadIdx.x;

    // zero this block's slice of g_sums (25600 / 592 ~= 44 floats)
    {
        const int per = (C * D + PA_BLOCKS - 1) / PA_BLOCKS;
        const int z0 = blockIdx.x * per;
        const int z1 = min(z0 + per, C * D);
        for (int i = z0 + tid; i < z1; i += blockDim.x) g_sums[i] = 0.0f;
    }

    const int is64 = block_is64((const unsigned int*)l32, N, tid);
    for (int i = tid; i < C; i += blockDim.x) h[i] = 0;
    if (tid < 128) sc[tid] = (tid < C) ? __ldg(&g_counti[tid]) : 0;
    __syncthreads();

    #pragma unroll
    for (int off = 1; off < 128; off <<= 1) {
        int t = (tid >= off && tid < 128) ? sc[tid - off] : 0;
        __syncthreads();
        if (tid < 128) sc[tid] += t;
        __syncthreads();
    }

    const int r0 = blockIdx.x * rows_per_block;
    const int r1 = min(r0 + rows_per_block, N);
    for (int i = r0 + tid; i < r1; i += blockDim.x)
        atomicAdd(&h[load_label(l32, i, is64)], 1);
    __syncthreads();

    for (int i = tid; i < C; i += blockDim.x) {
        const int start = sc[i] - __ldg(&g_counti[i]);   // exclusive scan
        base[i] = start + atomicAdd(&g_cursor[i], h[i]);
        h[i] = 0;
    }
    __syncthreads();
    for (int i = r0 + tid; i < r1; i += blockDim.x) {
        const int lab = load_label(l32, i, is64);
        const int loc = atomicAdd(&h[lab], 1);
        g_packed[base[lab] + loc] = (lab << 24) | i;
    }
}

// ---------------------------------------------------------------------------
// Pass B: segment-sum over class-sorted rows. EXACTLY ONE WAVE, now at
// 3 blocks/SM (444 blocks, __launch_bounds__(256,3) -> regs<=85, so batches
// shrink to 3 rows, depth-2). 24 warps/SM for latency coverage vs 16 before.
// Lane accumulates 8 dims (2x float4) in registers; flush to g_sums only on
// class change (~1/warp).
// ---------------------------------------------------------------------------
__global__ void __launch_bounds__(256, 3)
k_sum_sorted(const float* __restrict__ feat, int total, int chunk) {
    const int gw   = (int)((blockIdx.x * blockDim.x + threadIdx.x) >> 5);
    const int lane = threadIdx.x & 31;
    const int p0 = gw * chunk;
    const int p1 = min(p0 + chunk, total);
    if (p0 >= p1) return;

    float4 a0 = make_float4(0, 0, 0, 0);
    float4 a1 = make_float4(0, 0, 0, 0);
    int cur = __ldg(&g_packed[p0]) >> 24;

#define FLUSH()                                                               \
    do {                                                                      \
        float* dp = &g_sums[cur * D + (lane << 2)];                           \
        atomicAdd(dp + 0, a0.x); atomicAdd(dp + 1, a0.y);                     \
        atomicAdd(dp + 2, a0.z); atomicAdd(dp + 3, a0.w);                     \
        atomicAdd(dp + 128, a1.x); atomicAdd(dp + 129, a1.y);                 \
        atomicAdd(dp + 130, a1.z); atomicAdd(dp + 131, a1.w);                 \
        a0.x = a0.y = a0.z = a0.w = 0.0f;                                     \
        a1.x = a1.y = a1.z = a1.w = 0.0f;                                     \
    } while (0)

    int pkA[PB_B], pkB[PB_B];
    float4 vaA[PB_B], vbA[PB_B], vaB[PB_B], vbB[PB_B];

#define PLOAD(PK, VA, VB, P, M)                                               \
    do {                                                                      \
        _Pragma("unroll")                                                     \
        for (int j = 0; j < PB_B; j++) if (j < (M)) {                         \
            (PK)[j] = __ldg(&g_packed[(P) + j]);                              \
            const float4* f4 =                                                \
                (const float4*)(feat + (size_t)((PK)[j] & 0xFFFFFF) * D);     \
            (VA)[j] = __ldcs(&f4[lane]);                                      \
            (VB)[j] = __ldcs(&f4[lane + 32]);                                 \
        }                                                                     \
    } while (0)

#define PPROC(PK, VA, VB, M)                                                  \
    do {                                                                      \
        _Pragma("unroll")                                                     \
        for (int j = 0; j < PB_B; j++) if (j < (M)) {                         \
            const int lab = (PK)[j] >> 24;                                    \
            if (lab != cur) { FLUSH(); cur = lab; }                           \
            a0.x += (VA)[j].x; a0.y += (VA)[j].y;                             \
            a0.z += (VA)[j].z; a0.w += (VA)[j].w;                             \
            a1.x += (VB)[j].x; a1.y += (VB)[j].y;                             \
            a1.z += (VB)[j].z; a1.w += (VB)[j].w;                             \
        }                                                                     \
    } while (0)

    int p = p0;
    int m = min(PB_B, p1 - p);
    PLOAD(pkA, vaA, vbA, p, m);
    int pn = p + m;
    int useA = 1;
    while (pn < p1) {
        const int mn = min(PB_B, p1 - pn);
        if (useA) {
            PLOAD(pkB, vaB, vbB, pn, mn);
            PPROC(pkA, vaA, vbA, m);
        } else {
            PLOAD(pkA, vaA, vbA, pn, mn);
            PPROC(pkB, vaB, vbB, m);
        }
        useA ^= 1;
        pn += mn;
        m = mn;
    }
    if (useA) {
        PPROC(pkA, vaA, vbA, m);
    } else {
        PPROC(pkB, vaB, vbB, m);
    }
    FLUSH();

#undef PLOAD
#undef PPROC
#undef FLUSH
}

// ---------------------------------------------------------------------------
// k_dist: distance to own-class center, class-sorted order (measured-best
// config: 4 rows/warp, oversubscribed grid). Center row L1-resident within a
// class run; computed on the fly as sums*inv_cnt.
// ---------------------------------------------------------------------------
__global__ void __launch_bounds__(256)
k_dist(const float* __restrict__ feat, float* __restrict__ out, int N) {
    const int gw   = (int)((blockIdx.x * blockDim.x + threadIdx.x) >> 5);
    const int lane = threadIdx.x & 31;
    const int p0 = DIST_ROWS * gw;
    if (p0 >= N) return;
    const int nr = min(DIST_ROWS, N - p0);

    int pk[DIST_ROWS];
    #pragma unroll
    for (int j = 0; j < DIST_ROWS; j++)
        pk[j] = (j < nr) ? __ldg(&g_packed[p0 + j]) : __ldg(&g_packed[p0]);

    float4 fa[DIST_ROWS], fb[DIST_ROWS], sa[DIST_ROWS], sb[DIST_ROWS];
    #pragma unroll
    for (int j = 0; j < DIST_ROWS; j++) {
        const float4* f4 =
            (const float4*)(feat + (size_t)(pk[j] & 0xFFFFFF) * D);
        fa[j] = __ldcs(&f4[lane]);
        fb[j] = __ldcs(&f4[lane + 32]);
    }
    #pragma unroll
    for (int j = 0; j < DIST_ROWS; j++) {
        const float4* s4 = (const float4*)(g_sums + (size_t)(pk[j] >> 24) * D);
        sa[j] = __ldg(&s4[lane]);
        sb[j] = __ldg(&s4[lane + 32]);
    }

    float dsq[DIST_ROWS];
    #pragma unroll
    for (int j = 0; j < DIST_ROWS; j++) {
        const int cnt = __ldg(&g_counti[pk[j] >> 24]);
        const float inv = (cnt > 0) ? (1.0f / (float)cnt) : 0.0f;
        float s = 0.0f, dx;
        dx = fa[j].x - sa[j].x * inv; s = fmaf(dx, dx, s);
        dx = fa[j].y - sa[j].y * inv; s = fmaf(dx, dx, s);
        dx = fa[j].z - sa[j].z * inv; s = fmaf(dx, dx, s);
        dx = fa[j].w - sa[j].w * inv; s = fmaf(dx, dx, s);
        dx = fb[j].x - sb[j].x * inv; s = fmaf(dx, dx, s);
        dx = fb[j].y - sb[j].y * inv; s = fmaf(dx, dx, s);
        dx = fb[j].z - sb[j].z * inv; s = fmaf(dx, dx, s);
        dx = fb[j].w - sb[j].w * inv; s = fmaf(dx, dx, s);
        dsq[j] = s;
    }

    #pragma unroll
    for (int o = 16; o; o >>= 1) {
        #pragma unroll
        for (int j = 0; j < DIST_ROWS; j++)
            dsq[j] += __shfl_xor_sync(0xffffffffu, dsq[j], o);
    }
    if (lane == 0) {
        #pragma unroll
        for (int j = 0; j < DIST_ROWS; j++)
            if (j < nr) out[pk[j] & 0xFFFFFF] = sqrtf(dsq[j]);
    }
}

// ---------------------------------------------------------------------------
extern "C" void kernel_launch(void* const* d_in, const int* in_sizes, int n_in,
                              void* d_out, int out_size) {
    const float* feat = (const float*)d_in[0];
    const int*   l32  = (const int*)d_in[1];
    float* out = (float*)d_out;

    const int N = in_sizes[0] / D;             // 500000

    k_zero<<<1, 128>>>();
    {
        int rpb = (N + PA_BLOCKS - 1) / PA_BLOCKS;
        k_hist<<<PA_BLOCKS, 256>>>(l32, N, rpb);
    }
    {
        int rpb = (N + PA_BLOCKS - 1) / PA_BLOCKS;
        k_scatter<<<PA_BLOCKS, 256>>>(l32, N, rpb);
    }
    {
        const int warps = SUM_BLOCKS * 8;                 // 3552
        const int chunk = (N + warps - 1) / warps;        // 141
        k_sum_sorted<<<SUM_BLOCKS, 256>>>(feat, N, chunk);
    }
    {
        int rows_per_block = 8 * DIST_ROWS;     // 8 warps x 4 sorted rows
        int blocks = (N + rows_per_block - 1) / rows_per_block;
        k_dist<<<blocks, 256>>>(feat, out, N);
    }
}